// round 17
// baseline (speedup 1.0000x reference)
#include <cuda_runtime.h>

// out = y where 0 < y <= 1 else 0, y = x * w[col] + b[col]
// x: [8192, 4096] f32, w/b: [4096] f32. HBM-bound elementwise.
// R17: last unmeasured cell — default (.ca) x loads instead of __ldcs, else
//      exact R2 (flat 8192x256, ITEMS=4 front-batched reads, JIT __ldg w/b,
//      __stcs stores). Predicted neutral; closes the load-policy axis.
//      Plateau context: kernel 38.1+-0.5us == 7.07 TB/s wall-clock, ~88% of
//      HBM spec (mixed read+write DRAM ceiling), across 7 structural variants.

#define D_VEC 1024            // 4096 / 4, power of two
#define ITEMS 4               // float4s per thread
#define THREADS 256
#define CHUNK (THREADS * ITEMS)   // 1024 float4 per block == one D row

__device__ __forceinline__ float4 gate4(float4 xv, float4 wv, float4 bv)
{
    float4 y;
    y.x = fmaf(xv.x, wv.x, bv.x);
    y.y = fmaf(xv.y, wv.y, bv.y);
    y.z = fmaf(xv.z, wv.z, bv.z);
    y.w = fmaf(xv.w, wv.w, bv.w);
    y.x = (y.x > 0.0f && y.x <= 1.0f) ? y.x : 0.0f;
    y.y = (y.y > 0.0f && y.y <= 1.0f) ? y.y : 0.0f;
    y.z = (y.z > 0.0f && y.z <= 1.0f) ? y.z : 0.0f;
    y.w = (y.w > 0.0f && y.w <= 1.0f) ? y.w : 0.0f;
    return y;
}

__global__ void __launch_bounds__(THREADS)
gegate_kernel(const float4* __restrict__ x,
              const float4* __restrict__ w,
              const float4* __restrict__ b,
              float4* __restrict__ out)
{
    int base = blockIdx.x * CHUNK + threadIdx.x;

    // Front-batched DEFAULT loads (.ca) — only delta vs R2's __ldcs.
    float4 xv[ITEMS];
    #pragma unroll
    for (int i = 0; i < ITEMS; i++)
        xv[i] = x[base + i * THREADS];

    #pragma unroll
    for (int i = 0; i < ITEMS; i++) {
        int idx = base + i * THREADS;
        int col = idx & (D_VEC - 1);
        float4 wv = __ldg(&w[col]);
        float4 bv = __ldg(&b[col]);
        __stcs(&out[idx], gate4(xv[i], wv, bv));
    }
}

extern "C" void kernel_launch(void* const* d_in, const int* in_sizes, int n_in,
                              void* d_out, int out_size)
{
    const float4* x = (const float4*)d_in[0];
    const float4* w = (const float4*)d_in[1];
    const float4* b = (const float4*)d_in[2];
    float4* out = (float4*)d_out;

    int n_vec = out_size / 4;                     // 8388608
    int blocks = n_vec / CHUNK;                   // 8192 exactly

    gegate_kernel<<<blocks, THREADS>>>(x, w, b, out);
}